// round 1
// baseline (speedup 1.0000x reference)
#include <cuda_runtime.h>

#define NUM_LAYERS 16
#define KS 31
#define HH 1024
#define WW 1024
#define IMW (WW + KS - 1)   // 1054
#define NC 3
#define TAPS (KS * KS)      // 961
#define TILE 32
#define TDIM 256
#define PATCH (TILE + KS - 1)  // 62
#define SSTRIDE (PATCH + 3)    // 65 -> conflict-free for 4-row x 8-quad warp layout

typedef unsigned long long u64;

// weights transposed to [c][tap][layer] so the 16 layer weights of a tap are
// contiguous (loadable as 8x LDS.64 broadcast pairs)
__device__ float g_wT[NC * TAPS * NUM_LAYERS];

__device__ __forceinline__ u64 pack_dup(float v) {
    u64 r;
    asm("mov.b64 %0, {%1, %1};" : "=l"(r) : "f"(v));
    return r;
}
__device__ __forceinline__ void fma2(u64 &d, u64 a, u64 b) {
    // packed 2x fp32 FMA (sm_100+): d = a*b + d elementwise on {lo,hi}
    asm("fma.rn.f32x2 %0, %1, %2, %0;" : "+l"(d) : "l"(a), "l"(b));
}
__device__ __forceinline__ float2 unpack2(u64 v) {
    float2 f;
    asm("mov.b64 {%0, %1}, %2;" : "=f"(f.x), "=f"(f.y) : "l"(v));
    return f;
}

__global__ void transpose_w_kernel(const float* __restrict__ w) {
    int i = blockIdx.x * blockDim.x + threadIdx.x;
    if (i >= NC * NUM_LAYERS * TAPS) return;
    int o = i / TAPS;           // output channel 0..47  (= c*16 + l)
    int tap = i - o * TAPS;
    int c = o >> 4;
    int l = o & 15;
    g_wT[(c * TAPS + tap) * NUM_LAYERS + l] = w[i];
}

__global__ void __launch_bounds__(TDIM, 2)
blur_kernel(const float* __restrict__ img, const int* __restrict__ idxp,
            const float* __restrict__ alpha, float* __restrict__ out)
{
    __shared__ __align__(16) float wrow_s[2][KS * NUM_LAYERS];  // 2 x 1984 B
    __shared__ float img_s[PATCH * SSTRIDE];                    // 16120 B

    const int c   = blockIdx.z;
    const int tid = threadIdx.x;
    const int y0  = blockIdx.y * TILE;
    const int x0  = blockIdx.x * TILE;

    const float* wt = g_wT + c * TAPS * NUM_LAYERS;

    // stage img patch (62x62) into padded smem
    const float* imc = img + (size_t)c * (IMW * IMW) + (size_t)y0 * IMW + x0;
    #pragma unroll 4
    for (int i = tid; i < PATCH * PATCH; i += TDIM) {
        int r  = i / PATCH;
        int cc = i - r * PATCH;
        img_s[r * SSTRIDE + cc] = imc[r * IMW + cc];
    }
    // stage first weight row (ky = 0)
    for (int i = tid; i < KS * NUM_LAYERS; i += TDIM)
        wrow_s[0][i] = wt[i];
    __syncthreads();

    // warp layout: 4 rows x 8 quads; thread owns 4 consecutive x pixels
    const int row = tid >> 3;         // 0..31
    const int qx  = (tid & 7) << 2;   // 0,4,...,28

    // 16 layers as 8 packed f32x2 accumulators per pixel, 4 pixels
    u64 acc[4][8];
    #pragma unroll
    for (int p = 0; p < 4; ++p) {
        #pragma unroll
        for (int lp = 0; lp < 8; ++lp) acc[p][lp] = 0ull;
    }

    for (int ky = 0; ky < KS; ++ky) {
        const int cur = ky & 1;
        // prefetch next weight row into the other buffer (safe: consumers of
        // that buffer finished at the previous __syncthreads)
        if (ky + 1 < KS) {
            const float* src = wt + (ky + 1) * (KS * NUM_LAYERS);
            for (int i = tid; i < KS * NUM_LAYERS; i += TDIM)
                wrow_s[cur ^ 1][i] = src[i];
        }

        const float* ir = img_s + (row + ky) * SSTRIDE + qx;
        const u64*   wr = (const u64*)wrow_s[cur];

        #pragma unroll 4
        for (int kx = 0; kx < KS; ++kx) {
            u64 iv0 = pack_dup(ir[kx + 0]);
            u64 iv1 = pack_dup(ir[kx + 1]);
            u64 iv2 = pack_dup(ir[kx + 2]);
            u64 iv3 = pack_dup(ir[kx + 3]);
            const u64* wk = wr + kx * 8;
            #pragma unroll
            for (int lp = 0; lp < 8; ++lp) {
                u64 w2 = wk[lp];                  // LDS.64 broadcast
                fma2(acc[0][lp], iv0, w2);
                fma2(acc[1][lp], iv1, w2);
                fma2(acc[2][lp], iv2, w2);
                fma2(acc[3][lp], iv3, w2);
            }
        }
        __syncthreads();
    }

    // epilogue: out[c,y,x] = sum_l acc[l] * alpha[idx, l, y, x]
    const int idx = *idxp;
    const int y = y0 + row;
    const int x = x0 + qx;
    const float* al = alpha + ((size_t)idx * NUM_LAYERS) * (HH * WW)
                            + (size_t)y * WW + x;
    float o0 = 0.f, o1 = 0.f, o2 = 0.f, o3 = 0.f;
    #pragma unroll
    for (int lp = 0; lp < 8; ++lp) {
        const float4 a0 = *(const float4*)(al + (size_t)(2 * lp)     * (HH * WW));
        const float4 a1 = *(const float4*)(al + (size_t)(2 * lp + 1) * (HH * WW));
        float2 v0 = unpack2(acc[0][lp]);
        float2 v1 = unpack2(acc[1][lp]);
        float2 v2 = unpack2(acc[2][lp]);
        float2 v3 = unpack2(acc[3][lp]);
        o0 += v0.x * a0.x + v0.y * a1.x;
        o1 += v1.x * a0.y + v1.y * a1.y;
        o2 += v2.x * a0.z + v2.y * a1.z;
        o3 += v3.x * a0.w + v3.y * a1.w;
    }
    float* og = out + (size_t)c * (HH * WW) + (size_t)y * WW + x;
    *(float4*)og = make_float4(o0, o1, o2, o3);
}

extern "C" void kernel_launch(void* const* d_in, const int* in_sizes, int n_in,
                              void* d_out, int out_size) {
    const float* img   = (const float*)d_in[0];
    const int*   idxp  = (const int*)d_in[1];
    const float* w     = (const float*)d_in[2];
    const float* alpha = (const float*)d_in[3];
    float*       out   = (float*)d_out;

    transpose_w_kernel<<<(NC * NUM_LAYERS * TAPS + 255) / 256, 256>>>(w);

    dim3 grid(WW / TILE, HH / TILE, NC);
    blur_kernel<<<grid, TDIM>>>(img, idxp, alpha, out);
}